// round 12
// baseline (speedup 1.0000x reference)
#include <cuda_runtime.h>
#include <cuda_bf16.h>
#include <cstdint>

// Fused single kernel. 512 blocks x 256 threads (co-residency guaranteed:
// >=4 blocks/SM even at 64 regs -> 592 slots >= 512 blocks, spin is safe).
//   phase1: R4-proven unroll-4 LDG read loop, rowsums -> smem, smem segment
//           atomics -> global atomics; parallel finalize in last block.
//   phase2: proven streaming float4 writes from smem rowsums + table.

#define NROWS 131072
#define DIN   256
#define NSUB  64
#define RPB   256            // rows per block
#define BT    256            // 8 warps, 32 rows/warp
#define GRID  (NROWS / RPB)  // 512

__device__ float g_segsum[NSUB];   // zero-init; reset by finalize block
__device__ float g_segcnt[NSUB];
__device__ float g_stab[NSUB];     // 128 * relu(Gamma * mean_g)
__device__ float g_row0sum;
__device__ int   g_c1;             // phase-1 ticket
__device__ int   g_c2;             // epilogue ticket
__device__ int   g_flag;           // table-ready flag

__global__ __launch_bounds__(BT) void fused_kernel(
    const float* __restrict__ x,
    const int*   __restrict__ sub,
    const float* __restrict__ Gamma,
    const float* __restrict__ Lambda,
    float*       __restrict__ out)
{
    __shared__ float srow[RPB];
    __shared__ float ssum[NSUB];
    __shared__ float scnt[NSUB];
    __shared__ float stab[NSUB];
    __shared__ int   is_last;

    const int t = threadIdx.x, warp = t >> 5, lane = t & 31;
    const int rowbase = blockIdx.x * RPB + warp * 32;

    if (t < NSUB) { ssum[t] = 0.f; scnt[t] = 0.f; }
    __syncthreads();

    // ---- Phase 1: rowsums (R4-proven loop) ----
    #pragma unroll 1
    for (int j = 0; j < 32; j += 4) {
        float s0, s1, s2, s3;
        {
            const float4* p0 = reinterpret_cast<const float4*>(x + (size_t)(rowbase + j + 0) * DIN);
            const float4* p1 = reinterpret_cast<const float4*>(x + (size_t)(rowbase + j + 1) * DIN);
            const float4* p2 = reinterpret_cast<const float4*>(x + (size_t)(rowbase + j + 2) * DIN);
            const float4* p3 = reinterpret_cast<const float4*>(x + (size_t)(rowbase + j + 3) * DIN);
            float4 a0 = __ldcs(p0 + lane), b0 = __ldcs(p0 + lane + 32);
            float4 a1 = __ldcs(p1 + lane), b1 = __ldcs(p1 + lane + 32);
            float4 a2 = __ldcs(p2 + lane), b2 = __ldcs(p2 + lane + 32);
            float4 a3 = __ldcs(p3 + lane), b3 = __ldcs(p3 + lane + 32);
            s0 = (a0.x + a0.y) + (a0.z + a0.w) + (b0.x + b0.y) + (b0.z + b0.w);
            s1 = (a1.x + a1.y) + (a1.z + a1.w) + (b1.x + b1.y) + (b1.z + b1.w);
            s2 = (a2.x + a2.y) + (a2.z + a2.w) + (b2.x + b2.y) + (b2.z + b2.w);
            s3 = (a3.x + a3.y) + (a3.z + a3.w) + (b3.x + b3.y) + (b3.z + b3.w);
        }
        #pragma unroll
        for (int o = 16; o; o >>= 1) {
            s0 += __shfl_xor_sync(0xffffffffu, s0, o);
            s1 += __shfl_xor_sync(0xffffffffu, s1, o);
            s2 += __shfl_xor_sync(0xffffffffu, s2, o);
            s3 += __shfl_xor_sync(0xffffffffu, s3, o);
        }
        if (lane < 4) {
            const float sv = (lane == 0) ? s0 : (lane == 1) ? s1 : (lane == 2) ? s2 : s3;
            const int r = warp * 32 + j + lane;
            srow[r] = sv;
            if (rowbase + j + lane == 0) g_row0sum = sv;
            const int sg = __ldg(sub + rowbase + j + lane);
            atomicAdd(&ssum[sg], sv);
            atomicAdd(&scnt[sg], 1.f);
        }
    }
    __syncthreads();

    if (t < NSUB && scnt[t] != 0.f) {
        atomicAdd(&g_segsum[t], ssum[t]);
        atomicAdd(&g_segcnt[t], scnt[t]);
    }
    __syncthreads();

    // ---- Ticket + parallel finalize in last-arriving block ----
    if (t == 0) {
        __threadfence();
        is_last = (atomicAdd(&g_c1, 1) == GRID - 1) ? 1 : 0;
    }
    __syncthreads();

    if (is_last) {
        if (t < NSUB) {
            const float cnt = g_segcnt[t];
            const float m   = (cnt > 0.f) ? (g_segsum[t] / cnt) : g_row0sum;
            const float sv  = Gamma[0] * m;
            g_stab[t] = (sv > 0.f) ? 128.f * sv : 0.f;
            g_segsum[t] = 0.f;            // safe: only this block reads them
            g_segcnt[t] = 0.f;
        }
        __syncthreads();
        if (t == 0) {
            asm volatile("st.release.gpu.b32 [%0], %1;" :: "l"(&g_flag), "r"(1) : "memory");
        }
    } else if (t == 0) {
        int f;
        do {
            asm volatile("ld.acquire.gpu.b32 %0, [%1];" : "=r"(f) : "l"(&g_flag) : "memory");
            if (!f) __nanosleep(64);
        } while (!f);
    }
    __syncthreads();

    if (t < NSUB) stab[t] = g_stab[t];
    __syncthreads();

    // ---- Phase 2: streaming writes ----
    const float lam = Lambda[0];
    float4* obase = reinterpret_cast<float4*>(out) + (size_t)rowbase * (DIN / 4) + lane;

    #pragma unroll 4
    for (int j = 0; j < 32; j++) {
        const int r = warp * 32 + j;
        float o = lam * (srow[r] + stab[__ldg(sub + rowbase + j)]);
        o = (o > 0.f) ? o : 0.f;
        const float4 v = make_float4(o, o, o, o);
        float4* p = obase + (size_t)j * 64;
        __stcs(p, v);
        __stcs(p + 32, v);
    }

    // ---- Epilogue: last-departing block resets barrier state ----
    __syncthreads();
    if (t == 0) {
        __threadfence();
        if (atomicAdd(&g_c2, 1) == GRID - 1) {
            g_c1 = 0;
            g_c2 = 0;
            g_flag = 0;
            __threadfence();
        }
    }
}

extern "C" void kernel_launch(void* const* d_in, const int* in_sizes, int n_in,
                              void* d_out, int out_size)
{
    const float* x      = (const float*)d_in[0];
    const int*   sub    = (const int*)d_in[1];
    const float* Gamma  = (const float*)d_in[2];
    const float* Lambda = (const float*)d_in[3];
    float* out = (float*)d_out;

    fused_kernel<<<GRID, BT>>>(x, sub, Gamma, Lambda, out);
}